// round 3
// baseline (speedup 1.0000x reference)
#include <cuda_runtime.h>

#define TT   2048
#define NCTA 128
#define NTH  256

typedef unsigned long long ull;

__device__ __forceinline__ ull pk2(float lo, float hi) {
    ull r; asm("mov.b64 %0, {%1,%2};" : "=l"(r) : "f"(lo), "f"(hi)); return r;
}
__device__ __forceinline__ float losum(ull v) {
    float lo, hi; asm("mov.b64 {%0,%1}, %2;" : "=f"(lo), "=f"(hi) : "l"(v));
    return lo + hi;
}
__device__ __forceinline__ ull ff2(ull a, ull b, ull c) {
    ull d; asm("fma.rn.f32x2 %0, %1, %2, %3;" : "=l"(d) : "l"(a), "l"(b), "l"(c));
    return d;
}
__device__ __forceinline__ float ex2f(float x){ float y; asm("ex2.approx.f32 %0, %1;" : "=f"(y) : "f"(x)); return y; }
__device__ __forceinline__ float rcpf(float x){ float y; asm("rcp.approx.f32 %0, %1;" : "=f"(y) : "f"(x)); return y; }
__device__ __forceinline__ float sigm(float x){ return rcpf(1.f + ex2f(-1.4426950408889634f * x)); }
__device__ __forceinline__ float tanh_(float x){ float e = ex2f(2.8853900817779268f * x); return 1.f - 2.f * rcpf(e + 1.f); }

template<int NB>
__device__ __forceinline__ void gemv8(const float* __restrict__ w,
                                      const float* __restrict__ v, int pitchf,
                                      float bias, float* __restrict__ gout, bool gact)
{
    ull acc[8];
    const ull bini = pk2(bias, 0.f);
#pragma unroll
    for (int b = 0; b < 8; ++b) acc[b] = bini;
    const ulonglong2* wp = (const ulonglong2*)w;
#pragma unroll 2
    for (int kb = 0; kb < NB; ++kb) {
        const ulonglong2 wv = wp[kb];
#pragma unroll
        for (int b = 0; b < 8; ++b) {
            const ulonglong2 hv = ((const ulonglong2*)(v + b * pitchf))[kb];
            acc[b] = ff2(wv.x, hv.x, acc[b]);
            acc[b] = ff2(wv.y, hv.y, acc[b]);
        }
    }
#pragma unroll
    for (int b = 0; b < 8; b += 2) {
        float s0 = losum(acc[b]);
        float s1 = losum(acc[b + 1]);
        if (gact) { s0 = tanh_(s0); s1 = tanh_(s1); }
        else      { s0 = sigm(s0);  s1 = sigm(s1);  }
        *(float2*)(gout + b) = make_float2(s0, s1);
    }
}

// smem layout (float offsets)
#define OFF_W0 0
#define OFF_W1 11424
#define OFF_W2 32640
#define OFF_V0 53856
#define OFF_V1 54304
#define OFF_V2 55136
#define OFF_G  55968
#define OFF_WL 57600
#define OFF_BL 57704
#define SMEM_BYTES 230832

__global__ void __launch_bounds__(NTH, 1)
lstm_kernel(const float* __restrict__ inp,  const float* __restrict__ tim,
            const float* __restrict__ Wih0, const float* __restrict__ Whh0,
            const float* __restrict__ bih0, const float* __restrict__ bhh0,
            const float* __restrict__ Wih1, const float* __restrict__ Whh1,
            const float* __restrict__ bih1, const float* __restrict__ bhh1,
            const float* __restrict__ Wih2, const float* __restrict__ Whh2,
            const float* __restrict__ bih2, const float* __restrict__ bhh2,
            const float* __restrict__ Wlin, const float* __restrict__ blin,
            float* __restrict__ out)
{
    extern __shared__ float sm[];
    float* sW0 = sm + OFF_W0;  float* sW1 = sm + OFF_W1;  float* sW2 = sm + OFF_W2;
    float* sv0 = sm + OFF_V0;  float* sv1 = sm + OFF_V1;  float* sv2 = sm + OFF_V2;
    float* sg  = sm + OFF_G;   float* swl = sm + OFF_WL;  float* sbl = sm + OFF_BL;

    const int tid = threadIdx.x;
    const int gb0 = blockIdx.x * 8;

    // weights into smem (padded layouts)
    for (int i = tid; i < 204 * 56; i += NTH) {
        int r = i / 56, c = i - r * 56;
        float v = 0.f;
        if (c < 2)       v = Wih0[r * 2 + c];
        else if (c < 53) v = Whh0[r * 51 + (c - 2)];
        sW0[i] = v;
    }
    for (int i = tid; i < 204 * 104; i += NTH) {
        int r = i / 104, c = i - r * 104;
        float v = 0.f;
        if (c < 51)                  v = Wih1[r * 51 + c];
        else if (c >= 52 && c < 103) v = Whh1[r * 51 + (c - 52)];
        sW1[i] = v;
    }
    for (int i = tid; i < 204 * 104; i += NTH) {
        int r = i / 104, c = i - r * 104;
        float v = 0.f;
        if (c < 51)                  v = Wih2[r * 51 + c];
        else if (c >= 52 && c < 103) v = Whh2[r * 51 + (c - 52)];
        sW2[i] = v;
    }
    for (int i = tid; i < 8 * 54; i += NTH) {      // zero v0 cols 2..55
        int b = i / 54, c = 2 + (i - b * 54);
        sv0[b * 56 + c] = 0.f;
    }
    for (int i = tid; i < 8 * 104; i += NTH) { sv1[i] = 0.f; sv2[i] = 0.f; }
    for (int i = tid; i < 104; i += NTH) {
        int col = i / 52, kk = i - col * 52;
        swl[i] = (kk < 51) ? Wlin[col * 51 + kk] : 0.f;
    }
    if (tid < 2) sbl[tid] = blin[tid];
    if (tid >= 224 && tid < 240) {                 // x(t=0)
        int idx = tid - 224, b = idx & 7, sel = idx >> 3;
        const float* src = sel ? tim : inp;
        sv0[b * 56 + sel] = src[(gb0 + b) * TT];
    }

    const int r = tid;
    float bias0 = 0.f, bias1 = 0.f, bias2 = 0.f;
    bool gact = false; int k = 0, q = 0;
    if (r < 204) {
        bias0 = bih0[r] + bhh0[r];
        bias1 = bih1[r] + bhh1[r];
        bias2 = bih2[r] + bhh2[r];
        gact  = (r >= 102 && r < 153);
        k = r >> 2; q = r & 3;
    }
    float c0a = 0.f, c0b = 0.f, c1a = 0.f, c1b = 0.f, c2a = 0.f, c2b = 0.f;
    __syncthreads();

    for (int t = 0; t < TT; ++t) {
        // A0: L0 gates | head(t-1) | x(t+1) prefetch
        float xin = 0.f; int xb = 0, xsel = 0;
        if (tid >= 224 && tid < 240 && (t + 1) < TT) {
            int idx = tid - 224; xb = idx & 7; xsel = idx >> 3;
            const float* src = xsel ? tim : inp;
            xin = src[(gb0 + xb) * TT + (t + 1)];
        }
        if (r < 204) {
            gemv8<14>(sW0 + r * 56, sv0, 56, bias0, sg + r * 8, gact);
        } else if (tid >= 204 && tid < 220 && t > 0) {
            int idx = tid - 204, b = idx >> 1, col = idx & 1;
            float s = sbl[col];
            const float* h2 = sv2 + b * 104 + 52;
#pragma unroll 1
            for (int kk = 0; kk < 51; ++kk) s += swl[col * 52 + kk] * h2[kk];
            if (col) s = (s > 30.f) ? s : log1pf(__expf(s));
            out[((gb0 + b) * TT + (t - 1)) * 2 + col] = s;
        }
        __syncthreads();
        // B0: L0 update | x store
        if (r < 204) {
            float2 gi = *(float2*)(sg + k * 8 + 2 * q);
            float2 gf = *(float2*)(sg + (51 + k) * 8 + 2 * q);
            float2 gg = *(float2*)(sg + (102 + k) * 8 + 2 * q);
            float2 go = *(float2*)(sg + (153 + k) * 8 + 2 * q);
            int b0 = 2 * q, b1 = b0 + 1;
            c0a = gf.x * c0a + gi.x * gg.x;  float h0 = go.x * tanh_(c0a);
            c0b = gf.y * c0b + gi.y * gg.y;  float h1 = go.y * tanh_(c0b);
            sv0[b0 * 56 + 2 + k] = h0;  sv1[b0 * 104 + k] = h0;
            sv0[b1 * 56 + 2 + k] = h1;  sv1[b1 * 104 + k] = h1;
        } else if (tid >= 224 && tid < 240 && (t + 1) < TT) {
            sv0[xb * 56 + xsel] = xin;
        }
        __syncthreads();
        // A1
        if (r < 204) gemv8<26>(sW1 + r * 104, sv1, 104, bias1, sg + r * 8, gact);
        __syncthreads();
        // B1
        if (r < 204) {
            float2 gi = *(float2*)(sg + k * 8 + 2 * q);
            float2 gf = *(float2*)(sg + (51 + k) * 8 + 2 * q);
            float2 gg = *(float2*)(sg + (102 + k) * 8 + 2 * q);
            float2 go = *(float2*)(sg + (153 + k) * 8 + 2 * q);
            int b0 = 2 * q, b1 = b0 + 1;
            c1a = gf.x * c1a + gi.x * gg.x;  float h0 = go.x * tanh_(c1a);
            c1b = gf.y * c1b + gi.y * gg.y;  float h1 = go.y * tanh_(c1b);
            sv1[b0 * 104 + 52 + k] = h0;  sv2[b0 * 104 + k] = h0;
            sv1[b1 * 104 + 52 + k] = h1;  sv2[b1 * 104 + k] = h1;
        }
        __syncthreads();
        // A2
        if (r < 204) gemv8<26>(sW2 + r * 104, sv2, 104, bias2, sg + r * 8, gact);
        __syncthreads();
        // B2
        if (r < 204) {
            float2 gi = *(float2*)(sg + k * 8 + 2 * q);
            float2 gf = *(float2*)(sg + (51 + k) * 8 + 2 * q);
            float2 gg = *(float2*)(sg + (102 + k) * 8 + 2 * q);
            float2 go = *(float2*)(sg + (153 + k) * 8 + 2 * q);
            int b0 = 2 * q, b1 = b0 + 1;
            c2a = gf.x * c2a + gi.x * gg.x;  float h0 = go.x * tanh_(c2a);
            c2b = gf.y * c2b + gi.y * gg.y;  float h1 = go.y * tanh_(c2b);
            sv2[b0 * 104 + 52 + k] = h0;
            sv2[b1 * 104 + 52 + k] = h1;
        }
        __syncthreads();
    }
    // final head, t = TT-1
    if (tid >= 204 && tid < 220) {
        int idx = tid - 204, b = idx >> 1, col = idx & 1;
        float s = sbl[col];
        const float* h2 = sv2 + b * 104 + 52;
#pragma unroll 1
        for (int kk = 0; kk < 51; ++kk) s += swl[col * 52 + kk] * h2[kk];
        if (col) s = (s > 30.f) ? s : log1pf(__expf(s));
        out[((gb0 + b) * TT + (TT - 1)) * 2 + col] = s;
    }
}

extern "C" void kernel_launch(void* const* d_in, const int* in_sizes, int n_in,
                              void* d_out, int out_size)
{
    static bool attr_set = false;
    if (!attr_set) {
        cudaFuncSetAttribute(lstm_kernel,
                             cudaFuncAttributeMaxDynamicSharedMemorySize, SMEM_BYTES);
        attr_set = true;
    }
    lstm_kernel<<<NCTA, NTH, SMEM_BYTES>>>(
        (const float*)d_in[0],  (const float*)d_in[1],
        (const float*)d_in[2],  (const float*)d_in[3],
        (const float*)d_in[4],  (const float*)d_in[5],
        (const float*)d_in[6],  (const float*)d_in[7],
        (const float*)d_in[8],  (const float*)d_in[9],
        (const float*)d_in[10], (const float*)d_in[11],
        (const float*)d_in[12], (const float*)d_in[13],
        (const float*)d_in[14], (const float*)d_in[15],
        (float*)d_out);
}